// round 5
// baseline (speedup 1.0000x reference)
#include <cuda_runtime.h>
#include <math.h>

// Problem constants
#define Bc   2
#define Lc   2048
#define Dc   1024
#define Hc   16
#define HDc  64
#define Mtot (Bc*Lc)      // 4096 rows
#define BHL  (Bc*Hc*Lc)   // 65536

// ---- scratch (device globals: allocation-free, graph-capturable) ----
__device__ float g_q[(size_t)BHL*HDc];     // [B,H,L,HD]
__device__ float g_k[(size_t)BHL*HDc];
__device__ float g_v[(size_t)BHL*HDc];
__device__ float g_ctx[(size_t)Mtot*Dc];   // [B,L,D]
__device__ float g_x[(size_t)Mtot*Dc];     // pre-LN
__device__ float g_phase[BHL];             // raw phi per (b,h,l)

// ============================================================
// GEMM: out = A @ W^T + bias (+ residual for MODE 1)
// MODE 0: A = hidden_states [M,K]; z selects (Wq,Wk,Wv); scatter to [B,H,L,HD]
// MODE 1: A = g_ctx; W0 = Wo; out = g_x = ctx@Wo^T + bo + residual
// 128x128 tile, BK=16, 256 threads, 8x8 per-thread microtile.
// ============================================================
template<int MODE>
__global__ __launch_bounds__(256)
void gemm_kernel(const float* __restrict__ Ain,
                 const float* __restrict__ W0, const float* __restrict__ bias0,
                 const float* __restrict__ W1, const float* __restrict__ bias1,
                 const float* __restrict__ W2, const float* __restrict__ bias2,
                 const float* __restrict__ residual)
{
    const int K = Dc;
    const float* A;
    const float* W;
    const float* bias;
    float* out;
    if (MODE == 0) {
        A = Ain;
        int z = blockIdx.z;
        W    = (z == 0) ? W0    : (z == 1) ? W1    : W2;
        bias = (z == 0) ? bias0 : (z == 1) ? bias1 : bias2;
        out  = (z == 0) ? g_q   : (z == 1) ? g_k   : g_v;
    } else {
        A = g_ctx;
        W = W0; bias = bias0;
        out = g_x;
    }

    __shared__ float As[16][132];
    __shared__ float Bs[16][132];

    const int tid = threadIdx.x;
    const int m0 = blockIdx.y * 128;
    const int n0 = blockIdx.x * 128;
    const int tx = tid & 15, ty = tid >> 4;

    // global load mapping: 512 float4 per tile, 2 per thread
    const int id0 = tid, id1 = tid + 256;
    const int ra0 = id0 >> 2, ka0 = (id0 & 3) << 2;
    const int ra1 = id1 >> 2, ka1 = (id1 & 3) << 2;

    const float* Ap0 = A + (size_t)(m0 + ra0) * K + ka0;
    const float* Ap1 = A + (size_t)(m0 + ra1) * K + ka1;
    const float* Wp0 = W + (size_t)(n0 + ra0) * K + ka0;
    const float* Wp1 = W + (size_t)(n0 + ra1) * K + ka1;

    float acc[8][8];
    #pragma unroll
    for (int i = 0; i < 8; i++)
        #pragma unroll
        for (int j = 0; j < 8; j++) acc[i][j] = 0.f;

    for (int k0 = 0; k0 < K; k0 += 16) {
        float4 a0 = *(const float4*)(Ap0 + k0);
        float4 a1 = *(const float4*)(Ap1 + k0);
        float4 w0 = *(const float4*)(Wp0 + k0);
        float4 w1 = *(const float4*)(Wp1 + k0);
        __syncthreads();
        As[ka0+0][ra0] = a0.x; As[ka0+1][ra0] = a0.y; As[ka0+2][ra0] = a0.z; As[ka0+3][ra0] = a0.w;
        As[ka1+0][ra1] = a1.x; As[ka1+1][ra1] = a1.y; As[ka1+2][ra1] = a1.z; As[ka1+3][ra1] = a1.w;
        Bs[ka0+0][ra0] = w0.x; Bs[ka0+1][ra0] = w0.y; Bs[ka0+2][ra0] = w0.z; Bs[ka0+3][ra0] = w0.w;
        Bs[ka1+0][ra1] = w1.x; Bs[ka1+1][ra1] = w1.y; Bs[ka1+2][ra1] = w1.z; Bs[ka1+3][ra1] = w1.w;
        __syncthreads();
        #pragma unroll
        for (int kk = 0; kk < 16; kk++) {
            float a[8], b[8];
            *(float4*)&a[0] = *(const float4*)&As[kk][ty*8];
            *(float4*)&a[4] = *(const float4*)&As[kk][ty*8+4];
            *(float4*)&b[0] = *(const float4*)&Bs[kk][tx*8];
            *(float4*)&b[4] = *(const float4*)&Bs[kk][tx*8+4];
            #pragma unroll
            for (int i = 0; i < 8; i++)
                #pragma unroll
                for (int j = 0; j < 8; j++)
                    acc[i][j] += a[i] * b[j];
        }
    }

    #pragma unroll
    for (int i = 0; i < 8; i++) {
        const int m = m0 + ty*8 + i;
        #pragma unroll
        for (int j = 0; j < 8; j++) {
            const int n = n0 + tx*8 + j;
            float vv = acc[i][j] + bias[n];
            if (MODE == 0) {
                const int bb = m >> 11;          // / Lc
                const int l  = m & (Lc - 1);
                const int h  = n >> 6;           // / HDc
                const int d  = n & 63;
                out[(((size_t)bb*Hc + h)*Lc + l)*HDc + d] = vv;
            } else {
                vv += residual[(size_t)m*Dc + n];
                out[(size_t)m*Dc + n] = vv;
            }
        }
    }
}

// ============================================================
// Rotary + raw phase table. One thread per (b,h,l) row: rotates the
// full 64-dim q and k rows in place, stores raw phi into g_phase.
// phi layout: [B,L,H].
// ============================================================
__global__ __launch_bounds__(256)
void rotary_kernel(const float* __restrict__ phi)
{
    const int rest = blockIdx.x * blockDim.x + threadIdx.x;  // (b*H+h)*L + l
    if (rest >= BHL) return;
    const int l  = rest & (Lc - 1);
    const int bh = rest >> 11;
    const int h  = bh & (Hc - 1);
    const int b  = bh >> 4;

    const float p = phi[((size_t)b*Lc + l)*Hc + h];
    const float c = cosf(p);
    const float s = sinf(p);
    g_phase[rest] = p;

    // q row
    {
        float4* qp = (float4*)(g_q + (size_t)rest * HDc);
        float x[64];
        #pragma unroll
        for (int i = 0; i < 16; i++) *(float4*)&x[i*4] = qp[i];
        float r[64];
        #pragma unroll
        for (int d = 0; d < 32; d++) {
            r[d]      = x[d] * c - x[d + 32] * s;
            r[d + 32] = x[d + 32] * c + x[d] * s;
        }
        #pragma unroll
        for (int i = 0; i < 16; i++) qp[i] = *(float4*)&r[i*4];
    }
    // k row
    {
        float4* kp = (float4*)(g_k + (size_t)rest * HDc);
        float x[64];
        #pragma unroll
        for (int i = 0; i < 16; i++) *(float4*)&x[i*4] = kp[i];
        float r[64];
        #pragma unroll
        for (int d = 0; d < 32; d++) {
            r[d]      = x[d] * c - x[d + 32] * s;
            r[d + 32] = x[d + 32] * c + x[d] * s;
        }
        #pragma unroll
        for (int i = 0; i < 16; i++) kp[i] = *(float4*)&r[i*4];
    }
}

// ============================================================
// Flash-style attention. grid (Lc/128, Hc, Bc), 128 threads,
// one query row per thread. K/V streamed through smem in chunks of CK.
// sync mask computed LITERALLY as reference: cosf(phi_q - phi_k) < -0.7
// and q != k  ->  -1e9.
// ============================================================
#define CK 32

__global__ __launch_bounds__(128)
void attn_kernel(const float* __restrict__ amask)
{
    const int b  = blockIdx.z;
    const int h  = blockIdx.y;
    const int qi = blockIdx.x * 128 + threadIdx.x;
    const int bh = b * Hc + h;
    const size_t headoff = (size_t)bh * Lc * HDc;

    // q row into registers
    float q[64];
    {
        const float4* qp = (const float4*)(g_q + headoff + (size_t)qi * HDc);
        #pragma unroll
        for (int i = 0; i < 16; i++) *(float4*)&q[i*4] = qp[i];
    }
    const float pq = g_phase[(size_t)bh*Lc + qi];

    float m = -3.4e38f, lsum = 0.f;
    float o[64];
    #pragma unroll
    for (int i = 0; i < 64; i++) o[i] = 0.f;

    __shared__ float ks[CK][64];
    __shared__ float vs[CK][64];
    __shared__ float ph[CK], am[CK];

    const float4* kb0 = (const float4*)(g_k + headoff);
    const float4* vb0 = (const float4*)(g_v + headoff);

    for (int k0 = 0; k0 < Lc; k0 += CK) {
        __syncthreads();
        // load CK*64 floats = 512 float4 each for K and V; 4 per thread
        const int base4 = k0 * (HDc/4);
        #pragma unroll
        for (int it = 0; it < (CK*HDc/4)/128; it++) {
            const int idx = threadIdx.x + it * 128;
            ((float4*)&ks[0][0])[idx] = kb0[base4 + idx];
            ((float4*)&vs[0][0])[idx] = vb0[base4 + idx];
        }
        if (threadIdx.x < CK) {
            ph[threadIdx.x] = g_phase[(size_t)bh*Lc + k0 + threadIdx.x];
            am[threadIdx.x] = amask[(size_t)b*Lc + k0 + threadIdx.x];
        }
        __syncthreads();

        float p[CK];
        float cmax = -3.4e38f;
        #pragma unroll
        for (int j = 0; j < CK; j++) {
            const float4* kr = (const float4*)&ks[j][0];
            float s0 = 0.f, s1 = 0.f, s2 = 0.f, s3 = 0.f;
            #pragma unroll
            for (int d4 = 0; d4 < 16; d4++) {
                float4 kv = kr[d4];
                s0 += q[d4*4+0] * kv.x;
                s1 += q[d4*4+1] * kv.y;
                s2 += q[d4*4+2] * kv.z;
                s3 += q[d4*4+3] * kv.w;
            }
            float s = ((s0 + s1) + (s2 + s3)) * 0.125f;   // / sqrt(64)
            // literal reference mask: cos(phi_q - phi_k) < -0.7 and off-diagonal
            const float dc = cosf(pq - ph[j]);
            if (dc < -0.7f && (k0 + j) != qi) s = -1e9f;
            s += am[j];
            p[j] = s;
            cmax = fmaxf(cmax, s);
        }

        const float newm = fmaxf(m, cmax);
        const float corr = expf(m - newm);
        lsum *= corr;
        #pragma unroll
        for (int i = 0; i < 64; i++) o[i] *= corr;

        #pragma unroll
        for (int j = 0; j < CK; j++) {
            const float e = expf(p[j] - newm);
            lsum += e;
            const float4* vr = (const float4*)&vs[j][0];
            #pragma unroll
            for (int d4 = 0; d4 < 16; d4++) {
                float4 vv = vr[d4];
                o[d4*4+0] += e * vv.x;
                o[d4*4+1] += e * vv.y;
                o[d4*4+2] += e * vv.z;
                o[d4*4+3] += e * vv.w;
            }
        }
        m = newm;
    }

    const float invl = 1.f / lsum;
    float* cp = g_ctx + ((size_t)(b*Lc + qi))*Dc + h*HDc;
    #pragma unroll
    for (int i = 0; i < 64; i++) cp[i] = o[i] * invl;
}

// ============================================================
// LayerNorm over last dim (1024). one block per row, 256 threads.
// ============================================================
__global__ __launch_bounds__(256)
void ln_kernel(const float* __restrict__ gamma, const float* __restrict__ beta,
               float* __restrict__ out)
{
    const int row = blockIdx.x;
    const int tid = threadIdx.x;
    const float4 v = ((const float4*)(g_x + (size_t)row * Dc))[tid];
    float s  = v.x + v.y + v.z + v.w;
    float sq = v.x*v.x + v.y*v.y + v.z*v.z + v.w*v.w;
    #pragma unroll
    for (int off = 16; off > 0; off >>= 1) {
        s  += __shfl_xor_sync(0xffffffffu, s,  off);
        sq += __shfl_xor_sync(0xffffffffu, sq, off);
    }
    __shared__ float ssum[8], ssq[8];
    const int w = tid >> 5;
    if ((tid & 31) == 0) { ssum[w] = s; ssq[w] = sq; }
    __syncthreads();
    if (tid == 0) {
        float ts = 0.f, tq = 0.f;
        #pragma unroll
        for (int i = 0; i < 8; i++) { ts += ssum[i]; tq += ssq[i]; }
        ssum[0] = ts; ssq[0] = tq;
    }
    __syncthreads();
    const float mean = ssum[0] * (1.f / Dc);
    const float var  = ssq[0]  * (1.f / Dc) - mean * mean;
    const float inv  = rsqrtf(var + 1e-12f);
    const float4 gv = ((const float4*)gamma)[tid];
    const float4 bv = ((const float4*)beta)[tid];
    float4 ov;
    ov.x = (v.x - mean) * inv * gv.x + bv.x;
    ov.y = (v.y - mean) * inv * gv.y + bv.y;
    ov.z = (v.z - mean) * inv * gv.z + bv.z;
    ov.w = (v.w - mean) * inv * gv.w + bv.w;
    ((float4*)out)[(size_t)row * (Dc/4) + tid] = ov;
}

// ============================================================
// launch
// ============================================================
extern "C" void kernel_launch(void* const* d_in, const int* in_sizes, int n_in,
                              void* d_out, int out_size)
{
    const float* hs    = (const float*)d_in[0];
    const float* amask = (const float*)d_in[1];
    const float* phi   = (const float*)d_in[2];
    const float* Wq    = (const float*)d_in[3];
    const float* bq    = (const float*)d_in[4];
    const float* Wk    = (const float*)d_in[5];
    const float* bk    = (const float*)d_in[6];
    const float* Wv    = (const float*)d_in[7];
    const float* bv    = (const float*)d_in[8];
    const float* Wo    = (const float*)d_in[9];
    const float* bo    = (const float*)d_in[10];
    const float* lng   = (const float*)d_in[11];
    const float* lnb   = (const float*)d_in[12];
    float* out = (float*)d_out;

    // 1) QKV projections -> g_q/g_k/g_v in [B,H,L,HD]
    dim3 g0(Dc/128, Mtot/128, 3);
    gemm_kernel<0><<<g0, 256>>>(hs, Wq, bq, Wk, bk, Wv, bv, nullptr);

    // 2) rotary (in place on g_q/g_k) + raw phase table
    rotary_kernel<<<BHL/256, 256>>>(phi);

    // 3) attention -> g_ctx [B,L,D]
    dim3 g2(Lc/128, Hc, Bc);
    attn_kernel<<<g2, 128>>>(amask);

    // 4) output projection + residual -> g_x
    dim3 g3(Dc/128, Mtot/128, 1);
    gemm_kernel<1><<<g3, 256>>>(nullptr, Wo, bo, nullptr, nullptr, nullptr, nullptr, hs);

    // 5) layernorm -> d_out
    ln_kernel<<<Mtot, 256>>>(lng, lnb, out);
}

// round 6
// speedup vs baseline: 1.5474x; 1.5474x over previous
#include <cuda_runtime.h>
#include <math.h>

// Problem constants
#define Bc   2
#define Lc   2048
#define Dc   1024
#define Hc   16
#define HDc  64
#define Mtot (Bc*Lc)      // 4096 rows
#define BHL  (Bc*Hc*Lc)   // 65536

typedef unsigned long long ull;

// ---- packed f32x2 helpers (sm_103a) ----
__device__ __forceinline__ ull pk2(float lo, float hi) {
    ull r; asm("mov.b64 %0, {%1, %2};" : "=l"(r) : "f"(lo), "f"(hi)); return r;
}
__device__ __forceinline__ float2 upk2(ull v) {
    float2 r; asm("mov.b64 {%0, %1}, %2;" : "=f"(r.x), "=f"(r.y) : "l"(v)); return r;
}
__device__ __forceinline__ void fma2(ull &d, ull a, ull b) {
    asm("fma.rn.f32x2 %0, %1, %2, %0;" : "+l"(d) : "l"(a), "l"(b));
}
__device__ __forceinline__ void mul2(ull &d, ull a) {
    asm("mul.rn.f32x2 %0, %0, %1;" : "+l"(d) : "l"(a));
}
__device__ __forceinline__ void add2(ull &d, ull a) {
    asm("add.rn.f32x2 %0, %0, %1;" : "+l"(d) : "l"(a));
}

// ---- scratch (device globals: allocation-free, graph-capturable) ----
__device__ float  g_q[(size_t)BHL*HDc];     // [B,H,L,HD]  (pre-scaled by 0.125)
__device__ float  g_k[(size_t)BHL*HDc];
__device__ float  g_v[(size_t)BHL*HDc];
__device__ float  g_ctx[(size_t)Mtot*Dc];   // [B,L,D]
__device__ float  g_x[(size_t)Mtot*Dc];     // pre-LN
__device__ float2 g_cs[BHL];                // (cos phi, sin phi) per (b,h,l)

// ============================================================
// GEMM: out = A @ W^T + bias (+ residual for MODE 1)
// 128x128 tile, BK=16, 256 threads, 8x8 microtile, FFMA2 math,
// register prefetch of next K-tile across the math phase.
// ============================================================
template<int MODE>
__global__ __launch_bounds__(256)
void gemm_kernel(const float* __restrict__ Ain,
                 const float* __restrict__ W0, const float* __restrict__ bias0,
                 const float* __restrict__ W1, const float* __restrict__ bias1,
                 const float* __restrict__ W2, const float* __restrict__ bias2,
                 const float* __restrict__ residual)
{
    const int K = Dc;
    const float* A;
    const float* W;
    const float* bias;
    float* out;
    if (MODE == 0) {
        A = Ain;
        int z = blockIdx.z;
        W    = (z == 0) ? W0    : (z == 1) ? W1    : W2;
        bias = (z == 0) ? bias0 : (z == 1) ? bias1 : bias2;
        out  = (z == 0) ? g_q   : (z == 1) ? g_k   : g_v;
    } else {
        A = g_ctx;
        W = W0; bias = bias0;
        out = g_x;
    }

    __shared__ __align__(16) float As[16][132];
    __shared__ __align__(16) float Bs[16][132];

    const int tid = threadIdx.x;
    const int m0 = blockIdx.y * 128;
    const int n0 = blockIdx.x * 128;
    const int tx = tid & 15, ty = tid >> 4;

    // global load mapping: 512 float4 per tile, 2 per thread per matrix
    const int id0 = tid, id1 = tid + 256;
    const int ra0 = id0 >> 2, ka0 = (id0 & 3) << 2;
    const int ra1 = id1 >> 2, ka1 = (id1 & 3) << 2;

    const float* Ap0 = A + (size_t)(m0 + ra0) * K + ka0;
    const float* Ap1 = A + (size_t)(m0 + ra1) * K + ka1;
    const float* Wp0 = W + (size_t)(n0 + ra0) * K + ka0;
    const float* Wp1 = W + (size_t)(n0 + ra1) * K + ka1;

    ull acc2[8][4];
    #pragma unroll
    for (int i = 0; i < 8; i++)
        #pragma unroll
        for (int j = 0; j < 4; j++) acc2[i][j] = 0ULL;

    // prefetch tile 0
    float4 a0 = *(const float4*)(Ap0);
    float4 a1 = *(const float4*)(Ap1);
    float4 w0 = *(const float4*)(Wp0);
    float4 w1 = *(const float4*)(Wp1);

    for (int k0 = 0; k0 < K; k0 += 16) {
        __syncthreads();   // previous math done before overwriting smem
        As[ka0+0][ra0] = a0.x; As[ka0+1][ra0] = a0.y; As[ka0+2][ra0] = a0.z; As[ka0+3][ra0] = a0.w;
        As[ka1+0][ra1] = a1.x; As[ka1+1][ra1] = a1.y; As[ka1+2][ra1] = a1.z; As[ka1+3][ra1] = a1.w;
        Bs[ka0+0][ra0] = w0.x; Bs[ka0+1][ra0] = w0.y; Bs[ka0+2][ra0] = w0.z; Bs[ka0+3][ra0] = w0.w;
        Bs[ka1+0][ra1] = w1.x; Bs[ka1+1][ra1] = w1.y; Bs[ka1+2][ra1] = w1.z; Bs[ka1+3][ra1] = w1.w;
        // issue next tile's global loads: latency hidden by math below
        if (k0 + 16 < K) {
            a0 = *(const float4*)(Ap0 + k0 + 16);
            a1 = *(const float4*)(Ap1 + k0 + 16);
            w0 = *(const float4*)(Wp0 + k0 + 16);
            w1 = *(const float4*)(Wp1 + k0 + 16);
        }
        __syncthreads();
        #pragma unroll
        for (int kk = 0; kk < 16; kk++) {
            float4 af0 = *(const float4*)&As[kk][ty*8];
            float4 af1 = *(const float4*)&As[kk][ty*8+4];
            float4 bf0 = *(const float4*)&Bs[kk][tx*8];
            float4 bf1 = *(const float4*)&Bs[kk][tx*8+4];
            ull bp[4];
            bp[0] = pk2(bf0.x, bf0.y); bp[1] = pk2(bf0.z, bf0.w);
            bp[2] = pk2(bf1.x, bf1.y); bp[3] = pk2(bf1.z, bf1.w);
            float a8[8] = {af0.x, af0.y, af0.z, af0.w, af1.x, af1.y, af1.z, af1.w};
            #pragma unroll
            for (int i = 0; i < 8; i++) {
                ull av = pk2(a8[i], a8[i]);
                #pragma unroll
                for (int j = 0; j < 4; j++) fma2(acc2[i][j], av, bp[j]);
            }
        }
    }

    #pragma unroll
    for (int i = 0; i < 8; i++) {
        const int m = m0 + ty*8 + i;
        #pragma unroll
        for (int j2 = 0; j2 < 4; j2++) {
            float2 vv2 = upk2(acc2[i][j2]);
            #pragma unroll
            for (int u = 0; u < 2; u++) {
                const int n = n0 + tx*8 + j2*2 + u;
                float vv = (u ? vv2.y : vv2.x) + bias[n];
                if (MODE == 0) {
                    const int bb = m >> 11;          // / Lc
                    const int l  = m & (Lc - 1);
                    const int h  = n >> 6;           // / HDc
                    const int d  = n & 63;
                    out[(((size_t)bb*Hc + h)*Lc + l)*HDc + d] = vv;
                } else {
                    vv += residual[(size_t)m*Dc + n];
                    out[(size_t)m*Dc + n] = vv;
                }
            }
        }
    }
}

// ============================================================
// Rotary + (cos,sin) table. One thread per (b,h,l) row.
// q additionally pre-scaled by 0.125 (exact power of two -> the
// attention dot equals score/sqrt(64) bit-identically scaled).
// phi layout: [B,L,H].
// ============================================================
__global__ __launch_bounds__(256)
void rotary_kernel(const float* __restrict__ phi)
{
    const int rest = blockIdx.x * blockDim.x + threadIdx.x;  // (b*H+h)*L + l
    if (rest >= BHL) return;
    const int l  = rest & (Lc - 1);
    const int bh = rest >> 11;
    const int h  = bh & (Hc - 1);
    const int b  = bh >> 4;

    const float p = phi[((size_t)b*Lc + l)*Hc + h];
    const float c = cosf(p);
    const float s = sinf(p);
    g_cs[rest] = make_float2(c, s);

    // q row (rotate + exact *0.125)
    {
        float4* qp = (float4*)(g_q + (size_t)rest * HDc);
        float x[64];
        #pragma unroll
        for (int i = 0; i < 16; i++) *(float4*)&x[i*4] = qp[i];
        float r[64];
        #pragma unroll
        for (int d = 0; d < 32; d++) {
            r[d]      = (x[d] * c - x[d + 32] * s) * 0.125f;
            r[d + 32] = (x[d + 32] * c + x[d] * s) * 0.125f;
        }
        #pragma unroll
        for (int i = 0; i < 16; i++) qp[i] = *(float4*)&r[i*4];
    }
    // k row
    {
        float4* kp = (float4*)(g_k + (size_t)rest * HDc);
        float x[64];
        #pragma unroll
        for (int i = 0; i < 16; i++) *(float4*)&x[i*4] = kp[i];
        float r[64];
        #pragma unroll
        for (int d = 0; d < 32; d++) {
            r[d]      = x[d] * c - x[d + 32] * s;
            r[d + 32] = x[d + 32] * c + x[d] * s;
        }
        #pragma unroll
        for (int i = 0; i < 16; i++) kp[i] = *(float4*)&r[i*4];
    }
}

// ============================================================
// Flash-style attention, FFMA2 math. grid (Lc/128, Hc, Bc), 128 thr,
// one query row per thread. K/V streamed through smem in chunks of CK.
// sync mask: cos(dphi) = cq*ck + sq*sk < -0.7 and q != k -> -1e9.
// ============================================================
#define CK 32

__global__ __launch_bounds__(128)
void attn_kernel(const float* __restrict__ amask)
{
    const int b  = blockIdx.z;
    const int h  = blockIdx.y;
    const int qi = blockIdx.x * 128 + threadIdx.x;
    const int bh = b * Hc + h;
    const size_t headoff = (size_t)bh * Lc * HDc;

    // q row (pre-scaled) into packed registers
    ull q2[32];
    {
        const ulonglong2* qp = (const ulonglong2*)(g_q + headoff + (size_t)qi * HDc);
        #pragma unroll
        for (int i = 0; i < 16; i++) { ulonglong2 t = qp[i]; q2[2*i] = t.x; q2[2*i+1] = t.y; }
    }
    const float2 csq = g_cs[(size_t)bh*Lc + qi];

    float m = -3.4e38f, lsum = 0.f;
    ull o2[32];
    #pragma unroll
    for (int i = 0; i < 32; i++) o2[i] = 0ULL;

    __shared__ __align__(16) float ks[CK][64];
    __shared__ __align__(16) float vs[CK][64];
    __shared__ float2 cs_s[CK];
    __shared__ float  am_s[CK];

    const float4* kb0 = (const float4*)(g_k + headoff);
    const float4* vb0 = (const float4*)(g_v + headoff);

    for (int k0 = 0; k0 < Lc; k0 += CK) {
        __syncthreads();
        const int base4 = k0 * (HDc/4);
        #pragma unroll
        for (int it = 0; it < (CK*HDc/4)/128; it++) {
            const int idx = threadIdx.x + it * 128;
            ((float4*)&ks[0][0])[idx] = kb0[base4 + idx];
            ((float4*)&vs[0][0])[idx] = vb0[base4 + idx];
        }
        if (threadIdx.x < CK) {
            cs_s[threadIdx.x] = g_cs[(size_t)bh*Lc + k0 + threadIdx.x];
            am_s[threadIdx.x] = amask[(size_t)b*Lc + k0 + threadIdx.x];
        }
        __syncthreads();

        // ---- scores pass ----
        float p[CK];
        float cmax = -3.4e38f;
        #pragma unroll
        for (int j = 0; j < CK; j++) {
            const ulonglong2* kr = (const ulonglong2*)&ks[j][0];
            ull s0 = 0ULL, s1 = 0ULL, s2 = 0ULL, s3 = 0ULL;
            #pragma unroll
            for (int t = 0; t < 8; t++) {
                ulonglong2 kv  = kr[t];
                fma2(s0, q2[2*t],      kv.x);
                fma2(s1, q2[2*t + 1],  kv.y);
                ulonglong2 kv2 = kr[t + 8];
                fma2(s2, q2[2*t + 16], kv2.x);
                fma2(s3, q2[2*t + 17], kv2.y);
            }
            add2(s0, s1); add2(s2, s3); add2(s0, s2);
            float2 sf = upk2(s0);
            float s = sf.x + sf.y;                 // already scaled by 1/8 via q
            const float2 csk = cs_s[j];
            const float dc = fmaf(csq.x, csk.x, csq.y * csk.y);
            if (dc < -0.7f && (k0 + j) != qi) s = -1e9f;
            s += am_s[j];
            p[j] = s;
            cmax = fmaxf(cmax, s);
        }

        // ---- online softmax update (rescale only when max moves) ----
        if (cmax > m) {
            const float corr = __expf(m - cmax);
            m = cmax;
            lsum *= corr;
            const ull c2 = pk2(corr, corr);
            #pragma unroll
            for (int i = 0; i < 32; i++) mul2(o2[i], c2);
        }

        #pragma unroll
        for (int j = 0; j < CK; j++) {
            const float e = __expf(p[j] - m);
            lsum += e;
            const ull e2 = pk2(e, e);
            const ulonglong2* vr = (const ulonglong2*)&vs[j][0];
            #pragma unroll
            for (int t = 0; t < 16; t++) {
                ulonglong2 vv = vr[t];
                fma2(o2[2*t],   e2, vv.x);
                fma2(o2[2*t+1], e2, vv.y);
            }
        }
    }

    const float invl = 1.f / lsum;
    float* cp = g_ctx + ((size_t)(b*Lc + qi))*Dc + h*HDc;
    #pragma unroll
    for (int t = 0; t < 16; t++) {
        float2 v0 = upk2(o2[2*t]);
        float2 v1 = upk2(o2[2*t+1]);
        float4 ov = make_float4(v0.x*invl, v0.y*invl, v1.x*invl, v1.y*invl);
        ((float4*)cp)[t] = ov;
    }
}

// ============================================================
// LayerNorm over last dim (1024). one block per row, 256 threads.
// ============================================================
__global__ __launch_bounds__(256)
void ln_kernel(const float* __restrict__ gamma, const float* __restrict__ beta,
               float* __restrict__ out)
{
    const int row = blockIdx.x;
    const int tid = threadIdx.x;
    const float4 v = ((const float4*)(g_x + (size_t)row * Dc))[tid];
    float s  = v.x + v.y + v.z + v.w;
    float sq = v.x*v.x + v.y*v.y + v.z*v.z + v.w*v.w;
    #pragma unroll
    for (int off = 16; off > 0; off >>= 1) {
        s  += __shfl_xor_sync(0xffffffffu, s,  off);
        sq += __shfl_xor_sync(0xffffffffu, sq, off);
    }
    __shared__ float ssum[8], ssq[8];
    const int w = tid >> 5;
    if ((tid & 31) == 0) { ssum[w] = s; ssq[w] = sq; }
    __syncthreads();
    if (tid == 0) {
        float ts = 0.f, tq = 0.f;
        #pragma unroll
        for (int i = 0; i < 8; i++) { ts += ssum[i]; tq += ssq[i]; }
        ssum[0] = ts; ssq[0] = tq;
    }
    __syncthreads();
    const float mean = ssum[0] * (1.f / Dc);
    const float var  = ssq[0]  * (1.f / Dc) - mean * mean;
    const float inv  = rsqrtf(var + 1e-12f);
    const float4 gv = ((const float4*)gamma)[tid];
    const float4 bv = ((const float4*)beta)[tid];
    float4 ov;
    ov.x = (v.x - mean) * inv * gv.x + bv.x;
    ov.y = (v.y - mean) * inv * gv.y + bv.y;
    ov.z = (v.z - mean) * inv * gv.z + bv.z;
    ov.w = (v.w - mean) * inv * gv.w + bv.w;
    ((float4*)out)[(size_t)row * (Dc/4) + tid] = ov;
}

// ============================================================
// launch
// ============================================================
extern "C" void kernel_launch(void* const* d_in, const int* in_sizes, int n_in,
                              void* d_out, int out_size)
{
    const float* hs    = (const float*)d_in[0];
    const float* amask = (const float*)d_in[1];
    const float* phi   = (const float*)d_in[2];
    const float* Wq    = (const float*)d_in[3];
    const float* bq    = (const float*)d_in[4];
    const float* Wk    = (const float*)d_in[5];
    const float* bk    = (const float*)d_in[6];
    const float* Wv    = (const float*)d_in[7];
    const float* bv    = (const float*)d_in[8];
    const float* Wo    = (const float*)d_in[9];
    const float* bo    = (const float*)d_in[10];
    const float* lng   = (const float*)d_in[11];
    const float* lnb   = (const float*)d_in[12];
    float* out = (float*)d_out;

    // 1) QKV projections -> g_q/g_k/g_v in [B,H,L,HD]
    dim3 g0(Dc/128, Mtot/128, 3);
    gemm_kernel<0><<<g0, 256>>>(hs, Wq, bq, Wk, bk, Wv, bv, nullptr);

    // 2) rotary (in place, q pre-scaled) + (cos,sin) table
    rotary_kernel<<<BHL/256, 256>>>(phi);

    // 3) attention -> g_ctx [B,L,D]
    dim3 g2(Lc/128, Hc, Bc);
    attn_kernel<<<g2, 128>>>(amask);

    // 4) output projection + residual -> g_x
    dim3 g3(Dc/128, Mtot/128, 1);
    gemm_kernel<1><<<g3, 256>>>(nullptr, Wo, bo, nullptr, nullptr, nullptr, nullptr, hs);

    // 5) layernorm -> d_out
    ln_kernel<<<Mtot, 256>>>(lng, lnb, out);
}

// round 7
// speedup vs baseline: 3.0871x; 1.9950x over previous
#include <cuda_runtime.h>
#include <math.h>
#include <stdint.h>

// Problem constants
#define Bc   2
#define Lc   2048
#define Dc   1024
#define Hc   16
#define HDc  64
#define Mtot (Bc*Lc)      // 4096
#define BHL  (Bc*Hc*Lc)   // 65536

// ---- scratch (device globals: allocation-free, graph-capturable) ----
__device__ float  g_q[(size_t)BHL*HDc];     // [B,H,L,HD] (q pre-scaled by 0.125)
__device__ float  g_k[(size_t)BHL*HDc];
__device__ float  g_v[(size_t)BHL*HDc];
__device__ float  g_ctx[(size_t)Mtot*Dc];   // [B,L,D]
__device__ float  g_x[(size_t)Mtot*Dc];     // pre-LN
__device__ float2 g_cs[BHL];                // (cos phi, sin phi) per (b,h,l)

// ---- tf32 mma.sync (m16n8k8). Raw fp32 bits; HW truncates mantissa. ----
__device__ __forceinline__ void mma_tf32(float* c, const uint32_t* a,
                                         uint32_t b0, uint32_t b1)
{
    asm volatile(
        "mma.sync.aligned.m16n8k8.row.col.f32.tf32.tf32.f32 "
        "{%0,%1,%2,%3}, {%4,%5,%6,%7}, {%8,%9}, {%0,%1,%2,%3};"
        : "+f"(c[0]), "+f"(c[1]), "+f"(c[2]), "+f"(c[3])
        : "r"(a[0]), "r"(a[1]), "r"(a[2]), "r"(a[3]), "r"(b0), "r"(b1));
}

// ============================================================
// tf32 tile GEMM: out = A @ W^T + bias (+ residual for MODE 1)
// 128x128 tile, K-chunk 32, 256 thr = 8 warps (2m x 4n), warp tile 64x32.
// ============================================================
template<int MODE>
__global__ __launch_bounds__(256)
void gemm_kernel(const float* __restrict__ Ain,
                 const float* __restrict__ W0, const float* __restrict__ bias0,
                 const float* __restrict__ W1, const float* __restrict__ bias1,
                 const float* __restrict__ W2, const float* __restrict__ bias2,
                 const float* __restrict__ residual)
{
    const float* A; const float* W; const float* bias; float* out;
    if (MODE == 0) {
        A = Ain;
        int z = blockIdx.z;
        W    = (z == 0) ? W0    : (z == 1) ? W1    : W2;
        bias = (z == 0) ? bias0 : (z == 1) ? bias1 : bias2;
        out  = (z == 0) ? g_q   : (z == 1) ? g_k   : g_v;
    } else {
        A = g_ctx; W = W0; bias = bias0; out = g_x;
    }

    __shared__ __align__(16) float As[128][36];
    __shared__ __align__(16) float Ws[128][36];

    const int tid  = threadIdx.x;
    const int lane = tid & 31;
    const int wid  = tid >> 5;
    const int g    = lane >> 2, tg = lane & 3;
    const int warpM = wid & 1, warpN = wid >> 1;
    const int m0 = blockIdx.y * 128;
    const int n0 = blockIdx.x * 128;
    const int row  = tid >> 1;
    const int half = tid & 1;

    const float* Arow = A + (size_t)(m0 + row) * Dc + half * 16;
    const float* Wrow = W + (size_t)(n0 + row) * Dc + half * 16;

    float acc[4][4][4];
    #pragma unroll
    for (int mt = 0; mt < 4; mt++)
        #pragma unroll
        for (int nt = 0; nt < 4; nt++)
            #pragma unroll
            for (int i = 0; i < 4; i++) acc[mt][nt][i] = 0.f;

    float4 pa[4], pw[4];
    #pragma unroll
    for (int j = 0; j < 4; j++) {
        pa[j] = *(const float4*)(Arow + j * 4);
        pw[j] = *(const float4*)(Wrow + j * 4);
    }

    for (int k0 = 0; k0 < Dc; k0 += 32) {
        __syncthreads();
        #pragma unroll
        for (int j = 0; j < 4; j++) {
            *(float4*)&As[row][half * 16 + j * 4] = pa[j];
            *(float4*)&Ws[row][half * 16 + j * 4] = pw[j];
        }
        if (k0 + 32 < Dc) {
            #pragma unroll
            for (int j = 0; j < 4; j++) {
                pa[j] = *(const float4*)(Arow + k0 + 32 + j * 4);
                pw[j] = *(const float4*)(Wrow + k0 + 32 + j * 4);
            }
        }
        __syncthreads();
        #pragma unroll
        for (int kk = 0; kk < 4; kk++) {
            uint32_t af[4][4], bf[4][2];
            #pragma unroll
            for (int mt = 0; mt < 4; mt++) {
                const int r0 = warpM * 64 + mt * 16 + g;
                af[mt][0] = __float_as_uint(As[r0    ][kk * 8 + tg]);
                af[mt][1] = __float_as_uint(As[r0 + 8][kk * 8 + tg]);
                af[mt][2] = __float_as_uint(As[r0    ][kk * 8 + tg + 4]);
                af[mt][3] = __float_as_uint(As[r0 + 8][kk * 8 + tg + 4]);
            }
            #pragma unroll
            for (int nt = 0; nt < 4; nt++) {
                const int c0 = warpN * 32 + nt * 8 + g;
                bf[nt][0] = __float_as_uint(Ws[c0][kk * 8 + tg]);
                bf[nt][1] = __float_as_uint(Ws[c0][kk * 8 + tg + 4]);
            }
            #pragma unroll
            for (int mt = 0; mt < 4; mt++)
                #pragma unroll
                for (int nt = 0; nt < 4; nt++)
                    mma_tf32(acc[mt][nt], af[mt], bf[nt][0], bf[nt][1]);
        }
    }

    // epilogue: thread owns rows (r, r+8), cols (n, n+1) per tile
    #pragma unroll
    for (int mt = 0; mt < 4; mt++) {
        const int mA = m0 + warpM * 64 + mt * 16 + g;
        #pragma unroll
        for (int nt = 0; nt < 4; nt++) {
            const int n = n0 + warpN * 32 + nt * 8 + 2 * tg;
            const float b0v = bias[n], b1v = bias[n + 1];
            #pragma unroll
            for (int rh = 0; rh < 2; rh++) {
                const int m = mA + rh * 8;
                float v0 = acc[mt][nt][rh * 2]     + b0v;
                float v1 = acc[mt][nt][rh * 2 + 1] + b1v;
                if (MODE == 0) {
                    const int bb = m >> 11;
                    const int l  = m & (Lc - 1);
                    const int h  = n >> 6;
                    const int d  = n & 63;
                    float2* dst = (float2*)&out[(((size_t)bb*Hc + h)*Lc + l)*HDc + d];
                    *dst = make_float2(v0, v1);
                } else {
                    const float2 rr = *(const float2*)&residual[(size_t)m*Dc + n];
                    *(float2*)&out[(size_t)m*Dc + n] = make_float2(v0 + rr.x, v1 + rr.y);
                }
            }
        }
    }
}

// ============================================================
// Rotary + (cos,sin) table. One thread per (b,h,l) row.
// q pre-scaled by 0.125 (exact). phi layout: [B,L,H].
// ============================================================
__global__ __launch_bounds__(256)
void rotary_kernel(const float* __restrict__ phi)
{
    const int rest = blockIdx.x * blockDim.x + threadIdx.x;  // (b*H+h)*L + l
    if (rest >= BHL) return;
    const int l  = rest & (Lc - 1);
    const int bh = rest >> 11;
    const int h  = bh & (Hc - 1);
    const int b  = bh >> 4;

    const float p = phi[((size_t)b*Lc + l)*Hc + h];
    const float c = cosf(p);
    const float s = sinf(p);
    g_cs[rest] = make_float2(c, s);

    {
        float4* qp = (float4*)(g_q + (size_t)rest * HDc);
        float x[64];
        #pragma unroll
        for (int i = 0; i < 16; i++) *(float4*)&x[i*4] = qp[i];
        float r[64];
        #pragma unroll
        for (int d = 0; d < 32; d++) {
            r[d]      = (x[d] * c - x[d + 32] * s) * 0.125f;
            r[d + 32] = (x[d + 32] * c + x[d] * s) * 0.125f;
        }
        #pragma unroll
        for (int i = 0; i < 16; i++) qp[i] = *(float4*)&r[i*4];
    }
    {
        float4* kp = (float4*)(g_k + (size_t)rest * HDc);
        float x[64];
        #pragma unroll
        for (int i = 0; i < 16; i++) *(float4*)&x[i*4] = kp[i];
        float r[64];
        #pragma unroll
        for (int d = 0; d < 32; d++) {
            r[d]      = x[d] * c - x[d + 32] * s;
            r[d + 32] = x[d + 32] * c + x[d] * s;
        }
        #pragma unroll
        for (int i = 0; i < 16; i++) kp[i] = *(float4*)&r[i*4];
    }
}

// ============================================================
// tf32 tensor-core flash attention.
// grid (Lc/64, Hc, Bc), 128 thr = 4 warps, 16 q-rows per warp.
// Dynamic smem: Qs(->Ps)[64][68] | Ks[64][68] | Vs[64][72] | csk[64] | am[64]
// ============================================================
#define QP 68
#define VP 72
#define ATTN_SMEM ((64*QP + 64*QP + 64*VP + 2*64 + 64) * 4)

__global__ __launch_bounds__(128)
void attn_kernel(const float* __restrict__ amask)
{
    extern __shared__ __align__(16) float sm[];
    float*  Qs  = sm;                    // [64][QP] -> reused as Ps
    float*  Ks  = Qs + 64 * QP;          // [64][QP]
    float*  Vs  = Ks + 64 * QP;          // [64][VP]
    float2* csk = (float2*)(Vs + 64 * VP);  // [64]
    float*  am  = (float*)(csk + 64);       // [64]

    const int tid  = threadIdx.x;
    const int lane = tid & 31;
    const int warp = tid >> 5;
    const int g    = lane >> 2, tg = lane & 3;

    const int b  = blockIdx.z;
    const int h  = blockIdx.y;
    const int q0 = blockIdx.x * 64;
    const int bh = b * Hc + h;
    const size_t headoff = (size_t)bh * Lc * HDc;
    const size_t bhL     = (size_t)bh * Lc;

    const int row  = tid >> 1;
    const int half = tid & 1;

    // --- stage Q tile ---
    {
        const float* src = g_q + headoff + (size_t)(q0 + row) * HDc + half * 32;
        #pragma unroll
        for (int j = 0; j < 8; j++)
            *(float4*)&Qs[row * QP + half * 32 + j * 4] = *(const float4*)(src + j * 4);
    }
    __syncthreads();

    // --- per-warp Q A-fragments (registers, whole kernel) ---
    uint32_t qa[8][4];
    const int qrow = warp * 16 + g;
    #pragma unroll
    for (int kk = 0; kk < 8; kk++) {
        qa[kk][0] = __float_as_uint(Qs[(qrow    ) * QP + kk * 8 + tg]);
        qa[kk][1] = __float_as_uint(Qs[(qrow + 8) * QP + kk * 8 + tg]);
        qa[kk][2] = __float_as_uint(Qs[(qrow    ) * QP + kk * 8 + tg + 4]);
        qa[kk][3] = __float_as_uint(Qs[(qrow + 8) * QP + kk * 8 + tg + 4]);
    }
    const float2 csq0 = g_cs[bhL + q0 + qrow];
    const float2 csq1 = g_cs[bhL + q0 + qrow + 8];
    const int qg0 = q0 + qrow, qg1 = q0 + qrow + 8;
    __syncthreads();   // Qs dead -> Ps

    float m0r = -3.4e38f, m1r = -3.4e38f;
    float l0r = 0.f, l1r = 0.f;
    float oacc[8][4];
    #pragma unroll
    for (int nt = 0; nt < 8; nt++)
        #pragma unroll
        for (int i = 0; i < 4; i++) oacc[nt][i] = 0.f;

    for (int kt = 0; kt < Lc; kt += 64) {
        __syncthreads();
        // --- stage K/V tiles ---
        {
            const float* ksrc = g_k + headoff + (size_t)(kt + row) * HDc + half * 32;
            const float* vsrc = g_v + headoff + (size_t)(kt + row) * HDc + half * 32;
            #pragma unroll
            for (int j = 0; j < 8; j++) {
                *(float4*)&Ks[row * QP + half * 32 + j * 4] = *(const float4*)(ksrc + j * 4);
                *(float4*)&Vs[row * VP + half * 32 + j * 4] = *(const float4*)(vsrc + j * 4);
            }
        }
        if (tid < 64) {
            csk[tid] = g_cs[bhL + kt + tid];
            am[tid]  = amask[(size_t)b * Lc + kt + tid];
        }
        __syncthreads();

        // --- scores: S[16 x 64] per warp ---
        float sacc[8][4];
        #pragma unroll
        for (int nt = 0; nt < 8; nt++) {
            #pragma unroll
            for (int i = 0; i < 4; i++) sacc[nt][i] = 0.f;
            const int krow = nt * 8 + g;
            #pragma unroll
            for (int kk = 0; kk < 8; kk++) {
                uint32_t b0 = __float_as_uint(Ks[krow * QP + kk * 8 + tg]);
                uint32_t b1 = __float_as_uint(Ks[krow * QP + kk * 8 + tg + 4]);
                mma_tf32(sacc[nt], qa[kk], b0, b1);
            }
        }

        // --- mask + online softmax ---
        float cmax0 = -3.4e38f, cmax1 = -3.4e38f;
        #pragma unroll
        for (int nt = 0; nt < 8; nt++) {
            const int c0 = nt * 8 + 2 * tg;
            const float2 ck0 = csk[c0], ck1 = csk[c0 + 1];
            const float a0 = am[c0], a1 = am[c0 + 1];
            const int kg0 = kt + c0, kg1 = kt + c0 + 1;

            float dc;
            dc = fmaf(csq0.x, ck0.x, csq0.y * ck0.y);
            if (dc < -0.7f && kg0 != qg0) sacc[nt][0] = -1e9f;
            dc = fmaf(csq0.x, ck1.x, csq0.y * ck1.y);
            if (dc < -0.7f && kg1 != qg0) sacc[nt][1] = -1e9f;
            dc = fmaf(csq1.x, ck0.x, csq1.y * ck0.y);
            if (dc < -0.7f && kg0 != qg1) sacc[nt][2] = -1e9f;
            dc = fmaf(csq1.x, ck1.x, csq1.y * ck1.y);
            if (dc < -0.7f && kg1 != qg1) sacc[nt][3] = -1e9f;

            sacc[nt][0] += a0; sacc[nt][1] += a1;
            sacc[nt][2] += a0; sacc[nt][3] += a1;
            cmax0 = fmaxf(cmax0, fmaxf(sacc[nt][0], sacc[nt][1]));
            cmax1 = fmaxf(cmax1, fmaxf(sacc[nt][2], sacc[nt][3]));
        }
        // quad reduce (lanes share g)
        cmax0 = fmaxf(cmax0, __shfl_xor_sync(0xffffffffu, cmax0, 1));
        cmax0 = fmaxf(cmax0, __shfl_xor_sync(0xffffffffu, cmax0, 2));
        cmax1 = fmaxf(cmax1, __shfl_xor_sync(0xffffffffu, cmax1, 1));
        cmax1 = fmaxf(cmax1, __shfl_xor_sync(0xffffffffu, cmax1, 2));

        if (cmax0 > m0r) {
            const float corr = __expf(m0r - cmax0);
            m0r = cmax0; l0r *= corr;
            #pragma unroll
            for (int nt = 0; nt < 8; nt++) { oacc[nt][0] *= corr; oacc[nt][1] *= corr; }
        }
        if (cmax1 > m1r) {
            const float corr = __expf(m1r - cmax1);
            m1r = cmax1; l1r *= corr;
            #pragma unroll
            for (int nt = 0; nt < 8; nt++) { oacc[nt][2] *= corr; oacc[nt][3] *= corr; }
        }

        #pragma unroll
        for (int nt = 0; nt < 8; nt++) {
            const int c0 = nt * 8 + 2 * tg;
            float p00 = __expf(sacc[nt][0] - m0r);
            float p01 = __expf(sacc[nt][1] - m0r);
            float p10 = __expf(sacc[nt][2] - m1r);
            float p11 = __expf(sacc[nt][3] - m1r);
            l0r += p00 + p01;
            l1r += p10 + p11;
            *(float2*)&Qs[(qrow    ) * QP + c0] = make_float2(p00, p01);
            *(float2*)&Qs[(qrow + 8) * QP + c0] = make_float2(p10, p11);
        }
        __syncwarp();

        // --- PV: O += P @ V ---
        #pragma unroll
        for (int kk = 0; kk < 8; kk++) {
            uint32_t pa[4];
            pa[0] = __float_as_uint(Qs[(qrow    ) * QP + kk * 8 + tg]);
            pa[1] = __float_as_uint(Qs[(qrow + 8) * QP + kk * 8 + tg]);
            pa[2] = __float_as_uint(Qs[(qrow    ) * QP + kk * 8 + tg + 4]);
            pa[3] = __float_as_uint(Qs[(qrow + 8) * QP + kk * 8 + tg + 4]);
            #pragma unroll
            for (int nt = 0; nt < 8; nt++) {
                uint32_t b0 = __float_as_uint(Vs[(kk * 8 + tg    ) * VP + nt * 8 + g]);
                uint32_t b1 = __float_as_uint(Vs[(kk * 8 + tg + 4) * VP + nt * 8 + g]);
                mma_tf32(oacc[nt], pa, b0, b1);
            }
        }
        __syncwarp();
    }

    // --- finalize ---
    l0r += __shfl_xor_sync(0xffffffffu, l0r, 1);
    l0r += __shfl_xor_sync(0xffffffffu, l0r, 2);
    l1r += __shfl_xor_sync(0xffffffffu, l1r, 1);
    l1r += __shfl_xor_sync(0xffffffffu, l1r, 2);
    const float inv0 = 1.f / l0r;
    const float inv1 = 1.f / l1r;

    float* c0p = g_ctx + ((size_t)(b * Lc + qg0)) * Dc + h * HDc;
    float* c1p = g_ctx + ((size_t)(b * Lc + qg1)) * Dc + h * HDc;
    #pragma unroll
    for (int nt = 0; nt < 8; nt++) {
        const int d = nt * 8 + 2 * tg;
        *(float2*)&c0p[d] = make_float2(oacc[nt][0] * inv0, oacc[nt][1] * inv0);
        *(float2*)&c1p[d] = make_float2(oacc[nt][2] * inv1, oacc[nt][3] * inv1);
    }
}

// ============================================================
// LayerNorm over last dim (1024). one block per row, 256 threads.
// ============================================================
__global__ __launch_bounds__(256)
void ln_kernel(const float* __restrict__ gamma, const float* __restrict__ beta,
               float* __restrict__ out)
{
    const int row = blockIdx.x;
    const int tid = threadIdx.x;
    const float4 v = ((const float4*)(g_x + (size_t)row * Dc))[tid];
    float s  = v.x + v.y + v.z + v.w;
    float sq = v.x*v.x + v.y*v.y + v.z*v.z + v.w*v.w;
    #pragma unroll
    for (int off = 16; off > 0; off >>= 1) {
        s  += __shfl_xor_sync(0xffffffffu, s,  off);
        sq += __shfl_xor_sync(0xffffffffu, sq, off);
    }
    __shared__ float ssum[8], ssq[8];
    const int w = tid >> 5;
    if ((tid & 31) == 0) { ssum[w] = s; ssq[w] = sq; }
    __syncthreads();
    if (tid == 0) {
        float ts = 0.f, tq = 0.f;
        #pragma unroll
        for (int i = 0; i < 8; i++) { ts += ssum[i]; tq += ssq[i]; }
        ssum[0] = ts; ssq[0] = tq;
    }
    __syncthreads();
    const float mean = ssum[0] * (1.f / Dc);
    const float var  = ssq[0]  * (1.f / Dc) - mean * mean;
    const float inv  = rsqrtf(var + 1e-12f);
    const float4 gv = ((const float4*)gamma)[tid];
    const float4 bv = ((const float4*)beta)[tid];
    float4 ov;
    ov.x = (v.x - mean) * inv * gv.x + bv.x;
    ov.y = (v.y - mean) * inv * gv.y + bv.y;
    ov.z = (v.z - mean) * inv * gv.z + bv.z;
    ov.w = (v.w - mean) * inv * gv.w + bv.w;
    ((float4*)out)[(size_t)row * (Dc/4) + tid] = ov;
}

// ============================================================
// launch
// ============================================================
extern "C" void kernel_launch(void* const* d_in, const int* in_sizes, int n_in,
                              void* d_out, int out_size)
{
    const float* hs    = (const float*)d_in[0];
    const float* amask = (const float*)d_in[1];
    const float* phi   = (const float*)d_in[2];
    const float* Wq    = (const float*)d_in[3];
    const float* bq    = (const float*)d_in[4];
    const float* Wk    = (const float*)d_in[5];
    const float* bk    = (const float*)d_in[6];
    const float* Wv    = (const float*)d_in[7];
    const float* bv    = (const float*)d_in[8];
    const float* Wo    = (const float*)d_in[9];
    const float* bo    = (const float*)d_in[10];
    const float* lng   = (const float*)d_in[11];
    const float* lnb   = (const float*)d_in[12];
    float* out = (float*)d_out;

    cudaFuncSetAttribute(attn_kernel,
                         cudaFuncAttributeMaxDynamicSharedMemorySize, ATTN_SMEM);

    // 1) QKV projections -> g_q/g_k/g_v in [B,H,L,HD]
    dim3 g0(Dc/128, Mtot/128, 3);
    gemm_kernel<0><<<g0, 256>>>(hs, Wq, bq, Wk, bk, Wv, bv, nullptr);

    // 2) rotary (in place, q pre-scaled) + (cos,sin) table
    rotary_kernel<<<BHL/256, 256>>>(phi);

    // 3) attention -> g_ctx [B,L,D]
    dim3 g2(Lc/64, Hc, Bc);
    attn_kernel<<<g2, 128, ATTN_SMEM>>>(amask);

    // 4) output projection + residual -> g_x
    dim3 g3(Dc/128, Mtot/128, 1);
    gemm_kernel<1><<<g3, 256>>>(nullptr, Wo, bo, nullptr, nullptr, nullptr, nullptr, hs);

    // 5) layernorm -> d_out
    ln_kernel<<<Mtot, 256>>>(lng, lnb, out);
}

// round 8
// speedup vs baseline: 4.2586x; 1.3795x over previous
#include <cuda_runtime.h>
#include <cuda_bf16.h>
#include <math.h>
#include <stdint.h>

// Problem constants
#define Bc   2
#define Lc   2048
#define Dc   1024
#define Hc   16
#define HDc  64
#define Mtot (Bc*Lc)      // 4096
#define BHL  (Bc*Hc*Lc)   // 65536

// ---- scratch (device globals: allocation-free, graph-capturable) ----
__device__ float  g_q[(size_t)BHL*HDc];     // [B,H,L,HD] (q pre-scaled by 0.125)
__device__ float  g_k[(size_t)BHL*HDc];     // [B,H,L,HD]
__device__ float  g_vt[(size_t)BHL*HDc];    // [B,H,HD,L]  (V transposed)
__device__ float  g_ctx[(size_t)Mtot*Dc];   // [B,L,D]
__device__ float  g_x[(size_t)Mtot*Dc];     // pre-LN
__device__ float2 g_cs[BHL];                // (cos phi, sin phi) per (b,h,l)

// ---- helpers ----
__device__ __forceinline__ uint32_t pkbf2(float lo, float hi) {
    __nv_bfloat162 h = __float22bfloat162_rn(make_float2(lo, hi));
    return *(uint32_t*)&h;
}
// bf16 mma m16n8k16, fp32 accumulate
__device__ __forceinline__ void mma_bf16(float* c, const uint32_t* a,
                                         uint32_t b0, uint32_t b1)
{
    asm volatile(
        "mma.sync.aligned.m16n8k16.row.col.f32.bf16.bf16.f32 "
        "{%0,%1,%2,%3}, {%4,%5,%6,%7}, {%8,%9}, {%0,%1,%2,%3};"
        : "+f"(c[0]), "+f"(c[1]), "+f"(c[2]), "+f"(c[3])
        : "r"(a[0]), "r"(a[1]), "r"(a[2]), "r"(a[3]), "r"(b0), "r"(b1));
}

// ============================================================
// bf16 tile GEMM: out = A @ W^T + bias (+ residual for MODE 1)
// 128x128 tile, K-chunk 32, 256 thr = 8 warps (2m x 4n), warp tile 64x32.
// A/W staged as bf16-pair uint32, row pad 20 (conflict-free frag loads).
// MODE 0, z==2 (V): epilogue writes TRANSPOSED [bh][d][l].
// ============================================================
template<int MODE>
__global__ __launch_bounds__(256)
void gemm_kernel(const float* __restrict__ Ain,
                 const float* __restrict__ W0, const float* __restrict__ bias0,
                 const float* __restrict__ W1, const float* __restrict__ bias1,
                 const float* __restrict__ W2, const float* __restrict__ bias2,
                 const float* __restrict__ residual)
{
    const float* A; const float* W; const float* bias; float* out;
    const int z = (MODE == 0) ? blockIdx.z : 0;
    if (MODE == 0) {
        A = Ain;
        W    = (z == 0) ? W0    : (z == 1) ? W1    : W2;
        bias = (z == 0) ? bias0 : (z == 1) ? bias1 : bias2;
        out  = (z == 0) ? g_q   : (z == 1) ? g_k   : g_vt;
    } else {
        A = g_ctx; W = W0; bias = bias0; out = g_x;
    }

    __shared__ uint32_t Au[128][20];
    __shared__ uint32_t Wu[128][20];

    const int tid  = threadIdx.x;
    const int lane = tid & 31;
    const int wid  = tid >> 5;
    const int g    = lane >> 2, tg = lane & 3;
    const int warpM = wid & 1, warpN = wid >> 1;
    const int m0 = blockIdx.y * 128;
    const int n0 = blockIdx.x * 128;
    const int row  = tid >> 1;
    const int half = tid & 1;

    const float* Arow = A + (size_t)(m0 + row) * Dc + half * 16;
    const float* Wrow = W + (size_t)(n0 + row) * Dc + half * 16;

    float acc[4][4][4];
    #pragma unroll
    for (int mt = 0; mt < 4; mt++)
        #pragma unroll
        for (int nt = 0; nt < 4; nt++)
            #pragma unroll
            for (int i = 0; i < 4; i++) acc[mt][nt][i] = 0.f;

    float4 pa[4], pw[4];
    #pragma unroll
    for (int j = 0; j < 4; j++) {
        pa[j] = *(const float4*)(Arow + j * 4);
        pw[j] = *(const float4*)(Wrow + j * 4);
    }

    for (int k0 = 0; k0 < Dc; k0 += 32) {
        __syncthreads();
        #pragma unroll
        for (int j = 0; j < 4; j++) {
            *(uint2*)&Au[row][half * 8 + j * 2] =
                make_uint2(pkbf2(pa[j].x, pa[j].y), pkbf2(pa[j].z, pa[j].w));
            *(uint2*)&Wu[row][half * 8 + j * 2] =
                make_uint2(pkbf2(pw[j].x, pw[j].y), pkbf2(pw[j].z, pw[j].w));
        }
        if (k0 + 32 < Dc) {
            #pragma unroll
            for (int j = 0; j < 4; j++) {
                pa[j] = *(const float4*)(Arow + k0 + 32 + j * 4);
                pw[j] = *(const float4*)(Wrow + k0 + 32 + j * 4);
            }
        }
        __syncthreads();
        #pragma unroll
        for (int ks = 0; ks < 2; ks++) {
            uint32_t af[4][4], bf[4][2];
            #pragma unroll
            for (int mt = 0; mt < 4; mt++) {
                const int r0 = warpM * 64 + mt * 16 + g;
                af[mt][0] = Au[r0    ][ks * 8 + tg];
                af[mt][1] = Au[r0 + 8][ks * 8 + tg];
                af[mt][2] = Au[r0    ][ks * 8 + tg + 4];
                af[mt][3] = Au[r0 + 8][ks * 8 + tg + 4];
            }
            #pragma unroll
            for (int nt = 0; nt < 4; nt++) {
                const int c0 = warpN * 32 + nt * 8 + g;
                bf[nt][0] = Wu[c0][ks * 8 + tg];
                bf[nt][1] = Wu[c0][ks * 8 + tg + 4];
            }
            #pragma unroll
            for (int mt = 0; mt < 4; mt++)
                #pragma unroll
                for (int nt = 0; nt < 4; nt++)
                    mma_bf16(acc[mt][nt], af[mt], bf[nt][0], bf[nt][1]);
        }
    }

    // epilogue
    #pragma unroll
    for (int mt = 0; mt < 4; mt++) {
        const int mA = m0 + warpM * 64 + mt * 16 + g;
        #pragma unroll
        for (int nt = 0; nt < 4; nt++) {
            const int n = n0 + warpN * 32 + nt * 8 + 2 * tg;
            const float b0v = bias[n], b1v = bias[n + 1];
            #pragma unroll
            for (int rh = 0; rh < 2; rh++) {
                const int m = mA + rh * 8;
                float v0 = acc[mt][nt][rh * 2]     + b0v;
                float v1 = acc[mt][nt][rh * 2 + 1] + b1v;
                if (MODE == 0) {
                    const int bb = m >> 11;
                    const int l  = m & (Lc - 1);
                    const int h  = n >> 6;
                    const int d  = n & 63;
                    if (z == 2) {
                        // transposed V: [bh][d][l]
                        float* base = &out[(((size_t)bb*Hc + h)*HDc + d)*Lc + l];
                        base[0]  = v0;
                        base[Lc] = v1;
                    } else {
                        *(float2*)&out[(((size_t)bb*Hc + h)*Lc + l)*HDc + d] =
                            make_float2(v0, v1);
                    }
                } else {
                    const float2 rr = *(const float2*)&residual[(size_t)m*Dc + n];
                    *(float2*)&out[(size_t)m*Dc + n] = make_float2(v0 + rr.x, v1 + rr.y);
                }
            }
        }
    }
}

// ============================================================
// Rotary + (cos,sin) table. One thread per (b,h,l) row.
// q pre-scaled by 0.125 (exact). phi layout: [B,L,H].
// ============================================================
__global__ __launch_bounds__(256)
void rotary_kernel(const float* __restrict__ phi)
{
    const int rest = blockIdx.x * blockDim.x + threadIdx.x;  // (b*H+h)*L + l
    if (rest >= BHL) return;
    const int l  = rest & (Lc - 1);
    const int bh = rest >> 11;
    const int h  = bh & (Hc - 1);
    const int b  = bh >> 4;

    const float p = phi[((size_t)b*Lc + l)*Hc + h];
    const float c = cosf(p);
    const float s = sinf(p);
    g_cs[rest] = make_float2(c, s);

    {
        float4* qp = (float4*)(g_q + (size_t)rest * HDc);
        float x[64];
        #pragma unroll
        for (int i = 0; i < 16; i++) *(float4*)&x[i*4] = qp[i];
        float r[64];
        #pragma unroll
        for (int d = 0; d < 32; d++) {
            r[d]      = (x[d] * c - x[d + 32] * s) * 0.125f;
            r[d + 32] = (x[d + 32] * c + x[d] * s) * 0.125f;
        }
        #pragma unroll
        for (int i = 0; i < 16; i++) qp[i] = *(float4*)&r[i*4];
    }
    {
        float4* kp = (float4*)(g_k + (size_t)rest * HDc);
        float x[64];
        #pragma unroll
        for (int i = 0; i < 16; i++) *(float4*)&x[i*4] = kp[i];
        float r[64];
        #pragma unroll
        for (int d = 0; d < 32; d++) {
            r[d]      = x[d] * c - x[d + 32] * s;
            r[d + 32] = x[d + 32] * c + x[d] * s;
        }
        #pragma unroll
        for (int i = 0; i < 16; i++) kp[i] = *(float4*)&r[i*4];
    }
}

// ============================================================
// bf16 tensor-core flash attention.
// grid (Lc/64, Hc, Bc), 128 thr = 4 warps, 16 q-rows per warp.
// smem: Ps (Q tile then P tiles), Ku (K tile), Vu (V^T tile), all
// bf16-pair uint32 with row pad 36 (banks (4*row+col)%32 conflict-free).
// Softmax / mask / normalization fully fp32.
// ============================================================
__global__ __launch_bounds__(128)
void attn_kernel(const float* __restrict__ amask)
{
    __shared__ uint32_t Ps[64][36];
    __shared__ uint32_t Ku[64][36];
    __shared__ uint32_t Vu[64][36];
    __shared__ float2 csk[64];
    __shared__ float  am[64];

    const int tid  = threadIdx.x;
    const int lane = tid & 31;
    const int warp = tid >> 5;
    const int g    = lane >> 2, tg = lane & 3;

    const int b  = blockIdx.z;
    const int h  = blockIdx.y;
    const int q0 = blockIdx.x * 64;
    const int bh = b * Hc + h;
    const size_t headoff = (size_t)bh * Lc * HDc;   // for g_q / g_k
    const size_t vtoff   = (size_t)bh * HDc * Lc;   // for g_vt
    const size_t bhL     = (size_t)bh * Lc;

    const int row  = tid >> 1;     // warp w covers rows 16w..16w+15
    const int half = tid & 1;

    // --- stage Q tile (bf16 pairs) into Ps ---
    {
        const float* src = g_q + headoff + (size_t)(q0 + row) * HDc + half * 32;
        #pragma unroll
        for (int j = 0; j < 8; j++) {
            float4 v = *(const float4*)(src + j * 4);
            *(uint2*)&Ps[row][half * 16 + j * 2] =
                make_uint2(pkbf2(v.x, v.y), pkbf2(v.z, v.w));
        }
    }
    __syncwarp();

    // --- per-warp Q A-fragments (registers, whole kernel) ---
    const int qrow = warp * 16 + g;
    uint32_t qa[4][4];
    #pragma unroll
    for (int ks = 0; ks < 4; ks++) {
        qa[ks][0] = Ps[qrow    ][ks * 8 + tg];
        qa[ks][1] = Ps[qrow + 8][ks * 8 + tg];
        qa[ks][2] = Ps[qrow    ][ks * 8 + tg + 4];
        qa[ks][3] = Ps[qrow + 8][ks * 8 + tg + 4];
    }
    const float2 csq0 = g_cs[bhL + q0 + qrow];
    const float2 csq1 = g_cs[bhL + q0 + qrow + 8];
    const int qg0 = q0 + qrow, qg1 = q0 + qrow + 8;
    __syncwarp();   // Ps (Q) consumed -> reusable for P

    float m0r = -3.4e38f, m1r = -3.4e38f;
    float l0r = 0.f, l1r = 0.f;
    float oacc[8][4];
    #pragma unroll
    for (int nt = 0; nt < 8; nt++)
        #pragma unroll
        for (int i = 0; i < 4; i++) oacc[nt][i] = 0.f;

    for (int kt = 0; kt < Lc; kt += 64) {
        __syncthreads();
        // --- stage K tile [key][hd] and V^T tile [d][key] as bf16 pairs ---
        {
            const float* ksrc = g_k  + headoff + (size_t)(kt + row) * HDc + half * 32;
            const float* vsrc = g_vt + vtoff   + (size_t)row * Lc + kt + half * 32;
            #pragma unroll
            for (int j = 0; j < 8; j++) {
                float4 kv = *(const float4*)(ksrc + j * 4);
                float4 vv = *(const float4*)(vsrc + j * 4);
                *(uint2*)&Ku[row][half * 16 + j * 2] =
                    make_uint2(pkbf2(kv.x, kv.y), pkbf2(kv.z, kv.w));
                *(uint2*)&Vu[row][half * 16 + j * 2] =
                    make_uint2(pkbf2(vv.x, vv.y), pkbf2(vv.z, vv.w));
            }
        }
        if (tid < 64) {
            csk[tid] = g_cs[bhL + kt + tid];
            am[tid]  = amask[(size_t)b * Lc + kt + tid];
        }
        __syncthreads();

        // --- scores: S[16 x 64] per warp ---
        float sacc[8][4];
        #pragma unroll
        for (int nt = 0; nt < 8; nt++) {
            #pragma unroll
            for (int i = 0; i < 4; i++) sacc[nt][i] = 0.f;
            const int krow = nt * 8 + g;
            #pragma unroll
            for (int ks = 0; ks < 4; ks++) {
                uint32_t b0 = Ku[krow][ks * 8 + tg];
                uint32_t b1 = Ku[krow][ks * 8 + tg + 4];
                mma_bf16(sacc[nt], qa[ks], b0, b1);
            }
        }

        // --- mask + online softmax (fp32, exact reference semantics) ---
        float cmax0 = -3.4e38f, cmax1 = -3.4e38f;
        #pragma unroll
        for (int nt = 0; nt < 8; nt++) {
            const int c0 = nt * 8 + 2 * tg;
            const float2 ck0 = csk[c0], ck1 = csk[c0 + 1];
            const float a0 = am[c0], a1 = am[c0 + 1];
            const int kg0 = kt + c0, kg1 = kt + c0 + 1;

            float dc;
            dc = fmaf(csq0.x, ck0.x, csq0.y * ck0.y);
            if (dc < -0.7f && kg0 != qg0) sacc[nt][0] = -1e9f;
            dc = fmaf(csq0.x, ck1.x, csq0.y * ck1.y);
            if (dc < -0.7f && kg1 != qg0) sacc[nt][1] = -1e9f;
            dc = fmaf(csq1.x, ck0.x, csq1.y * ck0.y);
            if (dc < -0.7f && kg0 != qg1) sacc[nt][2] = -1e9f;
            dc = fmaf(csq1.x, ck1.x, csq1.y * ck1.y);
            if (dc < -0.7f && kg1 != qg1) sacc[nt][3] = -1e9f;

            sacc[nt][0] += a0; sacc[nt][1] += a1;
            sacc[nt][2] += a0; sacc[nt][3] += a1;
            cmax0 = fmaxf(cmax0, fmaxf(sacc[nt][0], sacc[nt][1]));
            cmax1 = fmaxf(cmax1, fmaxf(sacc[nt][2], sacc[nt][3]));
        }
        cmax0 = fmaxf(cmax0, __shfl_xor_sync(0xffffffffu, cmax0, 1));
        cmax0 = fmaxf(cmax0, __shfl_xor_sync(0xffffffffu, cmax0, 2));
        cmax1 = fmaxf(cmax1, __shfl_xor_sync(0xffffffffu, cmax1, 1));
        cmax1 = fmaxf(cmax1, __shfl_xor_sync(0xffffffffu, cmax1, 2));

        if (cmax0 > m0r) {
            const float corr = __expf(m0r - cmax0);
            m0r = cmax0; l0r *= corr;
            #pragma unroll
            for (int nt = 0; nt < 8; nt++) { oacc[nt][0] *= corr; oacc[nt][1] *= corr; }
        }
        if (cmax1 > m1r) {
            const float corr = __expf(m1r - cmax1);
            m1r = cmax1; l1r *= corr;
            #pragma unroll
            for (int nt = 0; nt < 8; nt++) { oacc[nt][2] *= corr; oacc[nt][3] *= corr; }
        }

        #pragma unroll
        for (int nt = 0; nt < 8; nt++) {
            float p00 = __expf(sacc[nt][0] - m0r);
            float p01 = __expf(sacc[nt][1] - m0r);
            float p10 = __expf(sacc[nt][2] - m1r);
            float p11 = __expf(sacc[nt][3] - m1r);
            l0r += p00 + p01;
            l1r += p10 + p11;
            Ps[qrow    ][nt * 4 + tg] = pkbf2(p00, p01);
            Ps[qrow + 8][nt * 4 + tg] = pkbf2(p10, p11);
        }
        __syncwarp();

        // --- PV: O += P @ V  (A = P bf16, B = V^T bf16) ---
        #pragma unroll
        for (int ks = 0; ks < 4; ks++) {
            uint32_t pa[4];
            pa[0] = Ps[qrow    ][ks * 8 + tg];
            pa[1] = Ps[qrow + 8][ks * 8 + tg];
            pa[2] = Ps[qrow    ][ks * 8 + tg + 4];
            pa[3] = Ps[qrow + 8][ks * 8 + tg + 4];
            #pragma unroll
            for (int nt = 0; nt < 8; nt++) {
                const int vrow = nt * 8 + g;      // d index
                uint32_t b0 = Vu[vrow][ks * 8 + tg];
                uint32_t b1 = Vu[vrow][ks * 8 + tg + 4];
                mma_bf16(oacc[nt], pa, b0, b1);
            }
        }
        __syncwarp();
    }

    // --- finalize ---
    l0r += __shfl_xor_sync(0xffffffffu, l0r, 1);
    l0r += __shfl_xor_sync(0xffffffffu, l0r, 2);
    l1r += __shfl_xor_sync(0xffffffffu, l1r, 1);
    l1r += __shfl_xor_sync(0xffffffffu, l1r, 2);
    const float inv0 = 1.f / l0r;
    const float inv1 = 1.f / l1r;

    float* c0p = g_ctx + ((size_t)(b * Lc + qg0)) * Dc + h * HDc;
    float* c1p = g_ctx + ((size_t)(b * Lc + qg1)) * Dc + h * HDc;
    #pragma unroll
    for (int nt = 0; nt < 8; nt++) {
        const int d = nt * 8 + 2 * tg;
        *(float2*)&c0p[d] = make_float2(oacc[nt][0] * inv0, oacc[nt][1] * inv0);
        *(float2*)&c1p[d] = make_float2(oacc[nt][2] * inv1, oacc[nt][3] * inv1);
    }
}

// ============================================================
// LayerNorm over last dim (1024). one block per row, 256 threads.
// ============================================================
__global__ __launch_bounds__(256)
void ln_kernel(const float* __restrict__ gamma, const float* __restrict__ beta,
               float* __restrict__ out)
{
    const int row = blockIdx.x;
    const int tid = threadIdx.x;
    const float4 v = ((const float4*)(g_x + (size_t)row * Dc))[tid];
    float s  = v.x + v.y + v.z + v.w;
    float sq = v.x*v.x + v.y*v.y + v.z*v.z + v.w*v.w;
    #pragma unroll
    for (int off = 16; off > 0; off >>= 1) {
        s  += __shfl_xor_sync(0xffffffffu, s,  off);
        sq += __shfl_xor_sync(0xffffffffu, sq, off);
    }
    __shared__ float ssum[8], ssq[8];
    const int w = tid >> 5;
    if ((tid & 31) == 0) { ssum[w] = s; ssq[w] = sq; }
    __syncthreads();
    if (tid == 0) {
        float ts = 0.f, tq = 0.f;
        #pragma unroll
        for (int i = 0; i < 8; i++) { ts += ssum[i]; tq += ssq[i]; }
        ssum[0] = ts; ssq[0] = tq;
    }
    __syncthreads();
    const float mean = ssum[0] * (1.f / Dc);
    const float var  = ssq[0]  * (1.f / Dc) - mean * mean;
    const float inv  = rsqrtf(var + 1e-12f);
    const float4 gv = ((const float4*)gamma)[tid];
    const float4 bv = ((const float4*)beta)[tid];
    float4 ov;
    ov.x = (v.x - mean) * inv * gv.x + bv.x;
    ov.y = (v.y - mean) * inv * gv.y + bv.y;
    ov.z = (v.z - mean) * inv * gv.z + bv.z;
    ov.w = (v.w - mean) * inv * gv.w + bv.w;
    ((float4*)out)[(size_t)row * (Dc/4) + tid] = ov;
}

// ============================================================
// launch
// ============================================================
extern "C" void kernel_launch(void* const* d_in, const int* in_sizes, int n_in,
                              void* d_out, int out_size)
{
    const float* hs    = (const float*)d_in[0];
    const float* amask = (const float*)d_in[1];
    const float* phi   = (const float*)d_in[2];
    const float* Wq    = (const float*)d_in[3];
    const float* bq    = (const float*)d_in[4];
    const float* Wk    = (const float*)d_in[5];
    const float* bk    = (const float*)d_in[6];
    const float* Wv    = (const float*)d_in[7];
    const float* bv    = (const float*)d_in[8];
    const float* Wo    = (const float*)d_in[9];
    const float* bo    = (const float*)d_in[10];
    const float* lng   = (const float*)d_in[11];
    const float* lnb   = (const float*)d_in[12];
    float* out = (float*)d_out;

    // 1) QKV projections -> g_q/g_k (as [B,H,L,HD]) and g_vt (as [B,H,HD,L])
    dim3 g0(Dc/128, Mtot/128, 3);
    gemm_kernel<0><<<g0, 256>>>(hs, Wq, bq, Wk, bk, Wv, bv, nullptr);

    // 2) rotary (in place, q pre-scaled) + (cos,sin) table
    rotary_kernel<<<BHL/256, 256>>>(phi);

    // 3) attention -> g_ctx [B,L,D]
    dim3 g2(Lc/64, Hc, Bc);
    attn_kernel<<<g2, 128>>>(amask);

    // 4) output projection + residual -> g_x
    dim3 g3(Dc/128, Mtot/128, 1);
    gemm_kernel<1><<<g3, 256>>>(nullptr, Wo, bo, nullptr, nullptr, nullptr, nullptr, hs);

    // 5) layernorm -> d_out
    ln_kernel<<<Mtot, 256>>>(lng, lnb, out);
}